// round 1
// baseline (speedup 1.0000x reference)
#include <cuda_runtime.h>

// LocalizeAttention: out[bh, n, f, d] = x[bh, shift_f(n), d], zero at edges.
// Shapes fixed by the reference setup: b*h=16, H=W=D=24 (N=13824), d=32, 27 filters.
// Pure HBM-write-bound gather: 764 MB out + ~28 MB in.

#define HH 24
#define WW 24
#define DD 24
#define NN (HH * WW * DD)     // 13824
#define DM 32                  // feature dim (floats) -> 8 float4
#define FN 27
#define ROW4 8                 // float4 per (bh,n,f) row
#define PER_N (FN * ROW4)      // 216 float4 per (bh,n)

__global__ void __launch_bounds__(256)
localize_kernel(const float4* __restrict__ x, float4* __restrict__ out, int total4)
{
    int idx = blockIdx.x * 256 + threadIdx.x;
    if (idx >= total4) return;

    // idx = ((bh*N + n) * 27 + f) * 8 + d4   (all divisors compile-time constants)
    int bn  = idx / PER_N;          // bh*N + n
    int r   = idx - bn * PER_N;
    int f   = r >> 3;
    int d4  = r & 7;

    int bh  = bn / NN;
    int n   = bn - bh * NN;

    int i   = n / (WW * DD);
    int rem = n - i * (WW * DD);
    int j   = rem / DD;
    int k   = rem - j * DD;

    int fi  = f / 9;
    int fr  = f - fi * 9;
    int fj  = fr / 3;
    int fk  = fr - fj * 3;

    int ii = i + fi - 1;
    int jj = j + fj - 1;
    int kk = k + fk - 1;

    float4 v = make_float4(0.f, 0.f, 0.f, 0.f);
    if ((unsigned)ii < HH && (unsigned)jj < WW && (unsigned)kk < DD) {
        int np = (ii * WW + jj) * DD + kk;
        v = __ldg(&x[(size_t)(bh * NN + np) * ROW4 + d4]);
    }
    // Streaming store: output has zero reuse, don't pollute L2.
    __stcs(&out[idx], v);
}

extern "C" void kernel_launch(void* const* d_in, const int* in_sizes, int n_in,
                              void* d_out, int out_size)
{
    const float4* x = (const float4*)d_in[0];
    float4* out = (float4*)d_out;

    int total4 = out_size / 4;                 // BH*N*27*8 float4 elements
    int blocks = (total4 + 255) / 256;
    localize_kernel<<<blocks, 256>>>(x, out, total4);
}

// round 2
// speedup vs baseline: 1.0931x; 1.0931x over previous
#include <cuda_runtime.h>

// LocalizeAttention gather: out[bh, n, f, :] = x[bh, n + shift_f, :] (zero at edges).
// Shapes fixed by reference: BH=16, H=W=D=24 (N=13824), d=32 floats, 27 filters.
// One thread per (bh, n, d4-lane); 27 constant-offset predicated loads + 27 stores.

#define HH 24
#define WW 24
#define DD 24
#define NN (HH * WW * DD)      // 13824
#define FN 27
#define ROW4 8                 // float4 per feature row (32 floats)

__global__ void __launch_bounds__(256)
localize_kernel(const float4* __restrict__ x, float4* __restrict__ out, int total)
{
    int t = blockIdx.x * 256 + threadIdx.x;
    if (t >= total) return;

    // t = (bh*NN + n) * 8 + d4
    int d4 = t & 7;
    int bn = t >> 3;                // bh*NN + n
    int bh = bn / NN;
    int n  = bn - bh * NN;

    int i   = n / (WW * DD);
    int rem = n - i * (WW * DD);
    int j   = rem / DD;
    int k   = rem - j * DD;

    // Per-axis validity, computed once.
    bool ilo = (i >= 1), ihi = (i <= HH - 2);
    bool jlo = (j >= 1), jhi = (j <= WW - 2);
    bool klo = (k >= 1), khi = (k <= DD - 2);

    const float4* src = x + (size_t)bn * ROW4 + d4;
    float4* dst = out + (size_t)bn * (FN * ROW4) + d4;

    const float4 zero = make_float4(0.f, 0.f, 0.f, 0.f);

    #pragma unroll
    for (int fi = 0; fi < 3; fi++) {
        #pragma unroll
        for (int fj = 0; fj < 3; fj++) {
            #pragma unroll
            for (int fk = 0; fk < 3; fk++) {
                bool ok = (fi == 0 ? ilo : (fi == 2 ? ihi : true))
                       && (fj == 0 ? jlo : (fj == 2 ? jhi : true))
                       && (fk == 0 ? klo : (fk == 2 ? khi : true));
                // Source shift is a compile-time constant per filter.
                const int soff = ((fi - 1) * WW * DD + (fj - 1) * DD + (fk - 1)) * ROW4;
                float4 v = zero;
                if (ok) v = __ldg(src + soff);
                __stcs(dst + ((fi * 3 + fj) * 3 + fk) * ROW4, v);
            }
        }
    }
}

extern "C" void kernel_launch(void* const* d_in, const int* in_sizes, int n_in,
                              void* d_out, int out_size)
{
    const float4* x = (const float4*)d_in[0];
    float4* out = (float4*)d_out;

    // out_size = BH*N*27*32 floats; threads = BH*N*8 = out_size / (27*4)
    int total = out_size / (FN * 4);
    int blocks = (total + 255) / 256;
    localize_kernel<<<blocks, 256>>>(x, out, total);
}

// round 4
// speedup vs baseline: 1.1241x; 1.0284x over previous
#include <cuda_runtime.h>

// LocalizeAttention gather: out[bh, n, f, :] = x[bh, n + shift_f, :] (zero at edges).
// BH=16, H=W=D=24 (N=13824), d=32 floats, 27 filters.
// R3: SMEM-tiled. Block = (bh, i, 2 j-rows x full k). Loads 3x4x26 halo tile once
// (kills the 27x read amplification through L1/L2), serves all gathers from SMEM.

#define HH 24
#define WW 24
#define DD 24
#define NN (HH * WW * DD)      // 13824
#define FN 27
#define ROW4 8                 // float4 per feature row (32 floats)
#define JT 2                   // j-rows per block
#define LJ (JT + 2)            // 4 (with halo)
#define LK (DD + 2)            // 26 (with halo)
#define LROWS (3 * LJ * LK)    // 312 source rows in tile
#define THREADS 384            // = JT*DD*8 write lanes

__global__ void __launch_bounds__(THREADS)
localize_kernel(const float4* __restrict__ x, float4* __restrict__ out)
{
    __shared__ float4 s[LROWS * ROW4];   // 2496 float4 = 39936 B

    const int bh = blockIdx.z;
    const int i  = blockIdx.y;
    const int j0 = blockIdx.x * JT;
    const int t  = threadIdx.x;

    // ---- Load phase: tile + halo, zeros outside the volume ----
    const float4 zero = make_float4(0.f, 0.f, 0.f, 0.f);
    for (int l4 = t; l4 < LROWS * ROW4; l4 += THREADS) {
        int d4  = l4 & 7;
        int row = l4 >> 3;
        int li  = row / (LJ * LK);
        int r   = row - li * (LJ * LK);
        int lj  = r / LK;
        int lk  = r - lj * LK;
        int ii  = i  + li - 1;
        int jj  = j0 + lj - 1;
        int kk  = lk - 1;
        float4 v = zero;
        if ((unsigned)ii < HH && (unsigned)jj < WW && (unsigned)kk < DD) {
            v = __ldg(&x[((size_t)bh * NN + ii * (WW * DD) + jj * DD + kk) * ROW4 + d4]);
        }
        s[l4] = v;
    }
    __syncthreads();

    // ---- Write phase: one thread per (jl, k, d4); 27 SMEM reads + 27 streaming stores ----
    const int d4 = t & 7;
    const int nl = t >> 3;          // 0..47
    const int jl = nl / DD;         // 0..1
    const int k  = nl - jl * DD;    // 0..23

    const int n = i * (WW * DD) + (j0 + jl) * DD + k;
    float4* dst = out + ((size_t)bh * NN + n) * (FN * ROW4) + d4;
    const float4* sp = s + ((size_t)jl * LK + k) * ROW4 + d4;

    #pragma unroll
    for (int fi = 0; fi < 3; fi++) {
        #pragma unroll
        for (int fj = 0; fj < 3; fj++) {
            #pragma unroll
            for (int fk = 0; fk < 3; fk++) {
                // smem offset is a compile-time constant per filter
                const int soff = ((fi * LJ + fj) * LK + fk) * ROW4;
                __stcs(dst + ((fi * 3 + fj) * 3 + fk) * ROW4, sp[soff]);
            }
        }
    }
}

extern "C" void kernel_launch(void* const* d_in, const int* in_sizes, int n_in,
                              void* d_out, int out_size)
{
    const float4* x = (const float4*)d_in[0];
    float4* out = (float4*)d_out;

    int BH = out_size / (NN * FN * 32);     // batch*heads (16 for reference shapes)
    dim3 grid(WW / JT, HH, BH);
    localize_kernel<<<grid, THREADS>>>(x, out);
}